// round 15
// baseline (speedup 1.0000x reference)
#include <cuda_runtime.h>
#include <cstdint>
#include <math.h>
#include <mma.h>
#include <cuda_bf16.h>

using namespace nvcuda;

#define Cc    384
#define HEADS 12
#define HIDc  1536
#define Tt    65536          // total tokens = 16*64*64
#define EPSf  1e-5f

#define LDAH  72             // 64 k halfs + 8 pad -> conflict-free ldmatrix
#define LDC   132            // 128 + 4 pad (fp32 C tile)
#define SMEMB (4 * 128 * LDAH * 2)   // 73728 B: 2 stages x {A,B} bf16; C tile (67.6KB) fits

typedef __nv_bfloat16 bf16;

// ---------------- scratch (device globals; no allocation) ----------------
__device__ bf16  g_xw [(size_t)Tt * Cc];        // LN1 out (bf16)
__device__ bf16  g_qkv[(size_t)Tt * 3 * Cc];    // qkv (bf16)
__device__ bf16  g_at [(size_t)Tt * Cc];        // attention out (bf16)
__device__ bf16  g_pj [(size_t)Tt * Cc];        // proj out (bf16, window order)
__device__ bf16  g_h  [(size_t)Tt * Cc];        // LN2 out (bf16)
__device__ bf16  g_z1 [(size_t)Tt * HIDc];      // fc1 out (bf16)
__device__ bf16  g_z2 [(size_t)Tt * HIDc];      // dwconv out (bf16)
__device__ bf16  g_wq [1152 * 384];
__device__ bf16  g_wp [384 * 384];
__device__ bf16  g_w1 [1536 * 384];
__device__ bf16  g_w2 [384 * 1536];

__device__ __forceinline__ float gelu_fast(float x) {
    float u = 0.7978845608028654f * x * (1.0f + 0.044715f * x * x);
    float t;
    asm("tanh.approx.f32 %0, %1;" : "=f"(t) : "f"(u));
    return 0.5f * x * (1.0f + t);
}
__device__ __forceinline__ float warp_sum(float v) {
#pragma unroll
    for (int o = 16; o; o >>= 1) v += __shfl_xor_sync(0xffffffffu, v, o);
    return v;
}
__device__ __forceinline__ void cpa16(void* dst, const void* src) {
    unsigned int s = (unsigned int)__cvta_generic_to_shared(dst);
    asm volatile("cp.async.cg.shared.global [%0], [%1], 16;\n" :: "r"(s), "l"(src));
}
__device__ __forceinline__ void cpa_commit() { asm volatile("cp.async.commit_group;\n"); }
template <int N>
__device__ __forceinline__ void cpa_wait() { asm volatile("cp.async.wait_group %0;\n" :: "n"(N)); }

__device__ __forceinline__ void store4(float* p, float4 v) { *(float4*)p = v; }
__device__ __forceinline__ void store4(bf16* p, float4 v) {
    __nv_bfloat162 lo = __floats2bfloat162_rn(v.x, v.y);
    __nv_bfloat162 hi = __floats2bfloat162_rn(v.z, v.w);
    uint2 u; u.x = *(unsigned int*)&lo; u.y = *(unsigned int*)&hi;
    *(uint2*)p = u;
}
__device__ __forceinline__ float4 load4bf(const bf16* p) {
    uint2 raw = *(const uint2*)p;
    float2 a = __bfloat1622float2(*(__nv_bfloat162*)&raw.x);
    float2 b = __bfloat1622float2(*(__nv_bfloat162*)&raw.y);
    return make_float4(a.x, a.y, b.x, b.y);
}

// ---------------- fused f32 -> bf16 convert of all 4 weight matrices ----------------
#define WQ4 (1152 * 384 / 4)
#define WP4 (384 * 384 / 4)
#define W14 (1536 * 384 / 4)
#define W24 (384 * 1536 / 4)
__global__ void __launch_bounds__(256) f2bf_all(
        const float* __restrict__ qkv_w, const float* __restrict__ proj_w,
        const float* __restrict__ fc1_w, const float* __restrict__ fc2_w,
        bf16* __restrict__ wq, bf16* __restrict__ wp,
        bf16* __restrict__ w1, bf16* __restrict__ w2) {
    int i = blockIdx.x * 256 + threadIdx.x;
    const float* src; bf16* dst; int off;
    if (i < WQ4)                      { src = qkv_w;  dst = wq; off = i; }
    else if (i < WQ4 + WP4)           { src = proj_w; dst = wp; off = i - WQ4; }
    else if (i < WQ4 + WP4 + W14)     { src = fc1_w;  dst = w1; off = i - WQ4 - WP4; }
    else if (i < WQ4 + WP4 + W14 + W24) { src = fc2_w; dst = w2; off = i - WQ4 - WP4 - W14; }
    else return;
    float4 v = *(const float4*)(src + off * 4);
    store4(dst + off * 4, v);
}

// ---------------- 1) LN1 + roll(-4,-4) + window partition -> bf16 (float4) ----------------
__global__ void __launch_bounds__(256) ln1_shift_win(
        const float* __restrict__ x, const float* __restrict__ g,
        const float* __restrict__ b, bf16* __restrict__ xw) {
    int warp = threadIdx.x >> 5, lane = threadIdx.x & 31;
    int t = blockIdx.x * 8 + warp;
    int win = t >> 6, n = t & 63;
    int bi = win >> 6, wim = win & 63;
    int r = (((wim >> 3) << 3) + (n >> 3) + 4) & 63;
    int c = (((wim & 7) << 3) + (n & 7) + 4) & 63;
    const float* row = x + ((size_t)bi * 4096 + r * 64 + c) * Cc;
    float4 v[3]; float s = 0.f;
#pragma unroll
    for (int k = 0; k < 3; k++) {
        v[k] = *(const float4*)(row + lane * 4 + 128 * k);
        s += v[k].x + v[k].y + v[k].z + v[k].w;
    }
    s = warp_sum(s);
    float mean = s * (1.f / 384.f);
    float q = 0.f;
#pragma unroll
    for (int k = 0; k < 3; k++) {
        float dx = v[k].x - mean, dy = v[k].y - mean, dz = v[k].z - mean, dw = v[k].w - mean;
        q += dx * dx + dy * dy + dz * dz + dw * dw;
    }
    q = warp_sum(q);
    float rstd = rsqrtf(q * (1.f / 384.f) + EPSf);
    bf16* o = xw + (size_t)t * Cc;
#pragma unroll
    for (int k = 0; k < 3; k++) {
        int idx = lane * 4 + 128 * k;
        float4 gv = *(const float4*)(g + idx);
        float4 bv = *(const float4*)(b + idx);
        float4 ov;
        ov.x = (v[k].x - mean) * rstd * gv.x + bv.x;
        ov.y = (v[k].y - mean) * rstd * gv.y + bv.y;
        ov.z = (v[k].z - mean) * rstd * gv.z + bv.z;
        ov.w = (v[k].w - mean) * rstd * gv.w + bv.w;
        store4(o + idx, ov);
    }
}

// ---------------- 5) un-window + roll(+4,+4) + residual + LN2 (float4, no x1) ----------------
__global__ void __launch_bounds__(256) resid_ln2(
        const float* __restrict__ x, const bf16* __restrict__ proj,
        const float* __restrict__ g, const float* __restrict__ b,
        bf16* __restrict__ h) {
    int warp = threadIdx.x >> 5, lane = threadIdx.x & 31;
    int t = blockIdx.x * 8 + warp;
    int bi = t >> 12, l = t & 4095;
    int r = l >> 6, c = l & 63;
    int sr = (r - 4) & 63, sc = (c - 4) & 63;
    int win = bi * 64 + ((sr >> 3) << 3) + (sc >> 3);
    int nn = ((sr & 7) << 3) + (sc & 7);
    const bf16* pr = proj + ((size_t)win * 64 + nn) * Cc;
    const float* xr = x + (size_t)t * Cc;
    float4 v[3]; float s = 0.f;
#pragma unroll
    for (int k = 0; k < 3; k++) {
        int idx = lane * 4 + 128 * k;
        float4 xv = *(const float4*)(xr + idx);
        float4 pv = load4bf(pr + idx);
        v[k].x = xv.x + pv.x; v[k].y = xv.y + pv.y;
        v[k].z = xv.z + pv.z; v[k].w = xv.w + pv.w;
        s += v[k].x + v[k].y + v[k].z + v[k].w;
    }
    s = warp_sum(s);
    float mean = s * (1.f / 384.f);
    float q = 0.f;
#pragma unroll
    for (int k = 0; k < 3; k++) {
        float dx = v[k].x - mean, dy = v[k].y - mean, dz = v[k].z - mean, dw = v[k].w - mean;
        q += dx * dx + dy * dy + dz * dz + dw * dw;
    }
    q = warp_sum(q);
    float rstd = rsqrtf(q * (1.f / 384.f) + EPSf);
    bf16* o = h + (size_t)t * Cc;
#pragma unroll
    for (int k = 0; k < 3; k++) {
        int idx = lane * 4 + 128 * k;
        float4 gv = *(const float4*)(g + idx);
        float4 bv = *(const float4*)(b + idx);
        float4 ov;
        ov.x = (v[k].x - mean) * rstd * gv.x + bv.x;
        ov.y = (v[k].y - mean) * rstd * gv.y + bv.y;
        ov.z = (v[k].z - mean) * rstd * gv.z + bv.z;
        ov.w = (v[k].w - mean) * rstd * gv.w + bv.w;
        store4(o + idx, ov);
    }
}

// ---------------- 3) windowed attention: one (window, head) per block ----------------
// 128 thr = 4 warps; smem 32 KB: Q[64][40] bf16 @0 | K @5120 | V @10240 | S[64][68] f32 @15360.
#define ATT_SMEM 32768
__global__ void __launch_bounds__(128) attn_win(
        const bf16* __restrict__ qkv, const float* __restrict__ rpb,
        bf16* __restrict__ outp) {
    extern __shared__ char asm_[];
    __shared__ float rps[232];
    __shared__ int labs[64];
    int win = blockIdx.x;
    int head = blockIdx.y;
    int tid = threadIdx.x;
    int warp = tid >> 5;

    bf16* Q = (bf16*)(asm_);
    bf16* K = (bf16*)(asm_ + 5120);
    bf16* V = (bf16*)(asm_ + 10240);
    float* S = (float*)(asm_ + 15360);

    // cp.async Q,K,V loads: 64 rows x 4 16B-chunks per tile, 128 thr -> 2 per tile
#pragma unroll
    for (int i = 0; i < 2; i++) {
        int id = tid + 128 * i;
        int row = id >> 2, ch = (id & 3) * 8;
        const bf16* src = qkv + ((size_t)win * 64 + row) * (3 * Cc) + head * 32 + ch;
        cpa16(Q + row * 40 + ch, src);
        cpa16(K + row * 40 + ch, src + Cc);
        cpa16(V + row * 40 + ch, src + 2 * Cc);
    }
    cpa_commit();
    for (int i = tid; i < 225; i += 128) rps[i] = rpb[i * HEADS + head];
    if (tid < 64) {
        int n = tid;
        int wim = win & 63;
        int gr = ((wim >> 3) << 3) + (n >> 3);
        int gc = ((wim & 7) << 3) + (n & 7);
        labs[n] = (gr < 56 ? 0 : (gr < 60 ? 1 : 2)) * 3 + (gc < 56 ? 0 : (gc < 60 ? 1 : 2));
    }
    cpa_wait<0>();
    __syncthreads();

    // --- S = Q @ K^T (64x64x32): warp w does rows w*16..+15 ---
    {
        wmma::fragment<wmma::accumulator, 16, 16, 16, float> acc[4];
#pragma unroll
        for (int j = 0; j < 4; j++) wmma::fill_fragment(acc[j], 0.f);
#pragma unroll
        for (int kk = 0; kk < 32; kk += 16) {
            wmma::fragment<wmma::matrix_a, 16, 16, 16, bf16, wmma::row_major> fa;
            wmma::fragment<wmma::matrix_b, 16, 16, 16, bf16, wmma::col_major> fb[4];
            wmma::load_matrix_sync(fa, Q + (warp * 16) * 40 + kk, 40);
#pragma unroll
            for (int j = 0; j < 4; j++)
                wmma::load_matrix_sync(fb[j], K + (j * 16) * 40 + kk, 40);
#pragma unroll
            for (int j = 0; j < 4; j++)
                wmma::mma_sync(acc[j], fa, fb[j], acc[j]);
        }
#pragma unroll
        for (int j = 0; j < 4; j++)
            wmma::store_matrix_sync(S + (warp * 16) * 68 + j * 16, acc[j], 68,
                                    wmma::mem_row_major);
    }
    __syncthreads();

    // --- softmax: threads 0..63, one row each; float4 LDS; write P (bf16) over Q/K ---
    if (tid < 64) {
        int n = tid;
        bf16* P = (bf16*)asm_;
        const float SC = 0.17677669529663687f;   // 1/sqrt(32)
        int cvn = 15 * (n >> 3) + (n & 7);
        int myl = labs[n];
        float s[64];
        float mx = -1e30f;
#pragma unroll
        for (int m = 0; m < 64; m += 4) {
            float4 sv = *(const float4*)(S + n * 68 + m);
#pragma unroll
            for (int u = 0; u < 4; u++) {
                int mm = 63 - (m + u);
                int cvm = 15 * (mm >> 3) + (mm & 7);
                float a = (u == 0 ? sv.x : u == 1 ? sv.y : u == 2 ? sv.z : sv.w);
                a = a * SC + rps[cvn + cvm];
                a += (labs[m + u] != myl) ? -100.f : 0.f;
                s[m + u] = a;
                mx = fmaxf(mx, a);
            }
        }
        float sum = 0.f;
#pragma unroll
        for (int m = 0; m < 64; m++) { float e = __expf(s[m] - mx); s[m] = e; sum += e; }
        float inv = 1.f / sum;
#pragma unroll
        for (int m = 0; m < 64; m += 2) {
            __nv_bfloat162 pr2 = __floats2bfloat162_rn(s[m] * inv, s[m + 1] * inv);
            *(__nv_bfloat162*)(P + n * 72 + m) = pr2;
        }
    }
    __syncthreads();

    // --- O = P @ V (64x32x64): warp w rows w*16..+15; result into S ---
    {
        bf16* P = (bf16*)asm_;
        wmma::fragment<wmma::accumulator, 16, 16, 16, float> acc[2];
#pragma unroll
        for (int j = 0; j < 2; j++) wmma::fill_fragment(acc[j], 0.f);
#pragma unroll
        for (int kk = 0; kk < 64; kk += 16) {
            wmma::fragment<wmma::matrix_a, 16, 16, 16, bf16, wmma::row_major> fa;
            wmma::fragment<wmma::matrix_b, 16, 16, 16, bf16, wmma::row_major> fb[2];
            wmma::load_matrix_sync(fa, P + (warp * 16) * 72 + kk, 72);
#pragma unroll
            for (int j = 0; j < 2; j++)
                wmma::load_matrix_sync(fb[j], V + kk * 40 + j * 16, 40);
#pragma unroll
            for (int j = 0; j < 2; j++)
                wmma::mma_sync(acc[j], fa, fb[j], acc[j]);
        }
#pragma unroll
        for (int j = 0; j < 2; j++)
            wmma::store_matrix_sync(S + (warp * 16) * 68 + j * 16, acc[j], 68,
                                    wmma::mem_row_major);
    }
    __syncthreads();

#pragma unroll
    for (int i = 0; i < 4; i++) {
        int id = tid + 128 * i;
        int row = id >> 3, c4 = (id & 7) * 4;
        float4 v = *(const float4*)(S + row * 68 + c4);
        store4(outp + ((size_t)win * 64 + row) * Cc + head * 32 + c4, v);
    }
}

// ---------------- bf16 tensor-core GEMM, 2-stage cp.async, 3 CTAs/SM ----------------
// MODE 0: +bias  1: gelu(bn(+bias))
// MODE 2: gelu(bn(+bias)) + (x + unwindow(pj))  — recomputes the residual in-epilogue
template <int MODE, typename OUTT>
__global__ void __launch_bounds__(128, 3) hgemm(
        const bf16* __restrict__ A, const bf16* __restrict__ Wt,
        OUTT* __restrict__ Co, const float* __restrict__ bias,
        const float* __restrict__ bng, const float* __restrict__ bnb,
        const float* __restrict__ resx, const bf16* __restrict__ respj,
        int M, int Nn, int K) {
    extern __shared__ char smraw[];
    bf16* smh = (bf16*)smraw;
    bf16* Abuf[2] = { smh, smh + 2 * 128 * LDAH };
    bf16* Bbuf[2] = { smh + 128 * LDAH, smh + 3 * 128 * LDAH };

    int tid = threadIdx.x;
    int warp = tid >> 5;
    int wm = warp >> 1;
    int wn = warp & 1;
    int rowA = blockIdx.y * 128;
    int rowB = blockIdx.x * 128;

    wmma::fragment<wmma::accumulator, 16, 16, 16, float> acc[4][4];
#pragma unroll
    for (int i = 0; i < 4; i++)
#pragma unroll
        for (int j = 0; j < 4; j++) wmma::fill_fragment(acc[i][j], 0.f);

    int lrow = tid >> 3, lc = (tid & 7) * 8;
    const bf16* Ag = A  + (size_t)(rowA + lrow) * K + lc;
    const bf16* Bg = Wt + (size_t)(rowB + lrow) * K + lc;
    int nk = K >> 6;

    // prologue: stage 0
#pragma unroll
    for (int r = 0; r < 8; r++) {
        cpa16(Abuf[0] + (lrow + 16 * r) * LDAH + lc, Ag + (size_t)(16 * r) * K);
        cpa16(Bbuf[0] + (lrow + 16 * r) * LDAH + lc, Bg + (size_t)(16 * r) * K);
    }
    cpa_commit();

    for (int s = 0; s < nk; s++) {
        int cur = s & 1;
        if (s + 1 < nk) {
            int nb = cur ^ 1;
            int k0 = (s + 1) << 6;
#pragma unroll
            for (int r = 0; r < 8; r++) {
                cpa16(Abuf[nb] + (lrow + 16 * r) * LDAH + lc, Ag + (size_t)(16 * r) * K + k0);
                cpa16(Bbuf[nb] + (lrow + 16 * r) * LDAH + lc, Bg + (size_t)(16 * r) * K + k0);
            }
            cpa_commit();
            cpa_wait<1>();
        } else {
            cpa_wait<0>();
        }
        __syncthreads();
#pragma unroll
        for (int kk = 0; kk < 64; kk += 16) {
            wmma::fragment<wmma::matrix_a, 16, 16, 16, bf16, wmma::row_major> fa[4];
            wmma::fragment<wmma::matrix_b, 16, 16, 16, bf16, wmma::col_major> fb[4];
#pragma unroll
            for (int i = 0; i < 4; i++)
                wmma::load_matrix_sync(fa[i], Abuf[cur] + (wm * 64 + i * 16) * LDAH + kk, LDAH);
#pragma unroll
            for (int j = 0; j < 4; j++)
                wmma::load_matrix_sync(fb[j], Bbuf[cur] + (wn * 64 + j * 16) * LDAH + kk, LDAH);
#pragma unroll
            for (int i = 0; i < 4; i++)
#pragma unroll
                for (int j = 0; j < 4; j++)
                    wmma::mma_sync(acc[i][j], fa[i], fb[j], acc[i][j]);
        }
        __syncthreads();
    }

    // epilogue through fp32 smem C tile (reuses stage buffers)
    float* Cs = (float*)smraw;
#pragma unroll
    for (int i = 0; i < 4; i++)
#pragma unroll
        for (int j = 0; j < 4; j++)
            wmma::store_matrix_sync(Cs + (wm * 64 + i * 16) * LDC + wn * 64 + j * 16,
                                    acc[i][j], LDC, wmma::mem_row_major);
    __syncthreads();

    const float IS = rsqrtf(1.0f + EPSf);
    int q = tid & 31;
    int r0 = tid >> 5;
    int ncol = rowB + q * 4;
    float4 bv = *(const float4*)(bias + ncol);
    float4 gv = make_float4(0.f, 0.f, 0.f, 0.f), bb = gv;
    if (MODE >= 1) {
        gv = *(const float4*)(bng + ncol);
        bb = *(const float4*)(bnb + ncol);
        gv.x *= IS; gv.y *= IS; gv.z *= IS; gv.w *= IS;
    }
#pragma unroll
    for (int it = 0; it < 32; it++) {
        int r = r0 + it * 4;
        float4 v = *(const float4*)(Cs + r * LDC + q * 4);
        v.x += bv.x; v.y += bv.y; v.z += bv.z; v.w += bv.w;
        if (MODE >= 1) {
            v.x = gelu_fast(v.x * gv.x + bb.x);
            v.y = gelu_fast(v.y * gv.y + bb.y);
            v.z = gelu_fast(v.z * gv.z + bb.z);
            v.w = gelu_fast(v.w * gv.w + bb.w);
        }
        size_t off = (size_t)(rowA + r) * Nn + ncol;
        if (MODE == 2) {
            int t = rowA + r;
            int bi = t >> 12, l = t & 4095;
            int rr = l >> 6, cc = l & 63;
            int sr = (rr - 4) & 63, sc = (cc - 4) & 63;
            int win = bi * 64 + ((sr >> 3) << 3) + (sc >> 3);
            int nn = ((sr & 7) << 3) + (sc & 7);
            float4 xv = *(const float4*)(resx + off);
            float4 pv = load4bf(respj + ((size_t)win * 64 + nn) * Cc + ncol);
            v.x += xv.x + pv.x; v.y += xv.y + pv.y;
            v.z += xv.z + pv.z; v.w += xv.w + pv.w;
        }
        store4(Co + off, v);
    }
}

// ---------------- 7) NHWC depthwise 3x3 + BN + GELU, 4 pixels/thread ----------------
__global__ void __launch_bounds__(256) dwconv_bn_gelu(
        const bf16* __restrict__ z1, const float* __restrict__ wt,
        const float* __restrict__ wb, const float* __restrict__ bng,
        const float* __restrict__ bnb, bf16* __restrict__ z2) {
    __shared__ float ws[9][4][32];
    int c4l = threadIdx.x & 31;
    int p   = threadIdx.x >> 5;              // 0..7
    int ch  = (blockIdx.y * 32 + c4l) * 4;
    for (int i = threadIdx.x; i < 1152; i += 256) {
        int cc = i & 31;
        int l  = (i >> 5) & 3;
        int k  = i >> 7;
        ws[k][l][cc] = wt[(((blockIdx.y * 32 + cc) * 4) + l) * 9 + k];
    }
    __syncthreads();

    int pixbase = blockIdx.x * 32 + p * 4;
    int bi = pixbase >> 12; int rc = pixbase & 4095;
    int r = rc >> 6, c = rc & 63;
    float4 acc[4];
#pragma unroll
    for (int i = 0; i < 4; i++) acc[i] = make_float4(0.f, 0.f, 0.f, 0.f);

#pragma unroll
    for (int dr = -1; dr <= 1; dr++) {
        int rr = r + dr;
        if (rr < 0 || rr > 63) continue;
        const bf16* rowp = z1 + ((size_t)(bi * 4096 + rr * 64)) * HIDc + ch;
        int kb = (dr + 1) * 3;
#pragma unroll
        for (int j = -1; j <= 4; j++) {
            int cc = c + j;
            if (cc < 0 || cc > 63) continue;
            float4 v = load4bf(rowp + (size_t)cc * HIDc);
#pragma unroll
            for (int i = 0; i < 4; i++) {
                int d = j - i;
                if (d < -1 || d > 1) continue;
                int k = kb + d + 1;
                acc[i].x += v.x * ws[k][0][c4l];
                acc[i].y += v.y * ws[k][1][c4l];
                acc[i].z += v.z * ws[k][2][c4l];
                acc[i].w += v.w * ws[k][3][c4l];
            }
        }
    }
    const float IS = rsqrtf(1.0f + EPSf);
    float b0 = wb[ch + 0], b1 = wb[ch + 1], b2 = wb[ch + 2], b3 = wb[ch + 3];
    float g0 = bng[ch + 0] * IS, g1 = bng[ch + 1] * IS, g2 = bng[ch + 2] * IS, g3 = bng[ch + 3] * IS;
    float c0 = bnb[ch + 0], c1 = bnb[ch + 1], c2 = bnb[ch + 2], c3 = bnb[ch + 3];
#pragma unroll
    for (int i = 0; i < 4; i++) {
        float4 o;
        o.x = gelu_fast((acc[i].x + b0) * g0 + c0);
        o.y = gelu_fast((acc[i].y + b1) * g1 + c1);
        o.z = gelu_fast((acc[i].z + b2) * g2 + c2);
        o.w = gelu_fast((acc[i].w + b3) * g3 + c3);
        store4(z2 + (size_t)(pixbase + i) * HIDc + ch, o);
    }
}

// ---------------- launcher ----------------
extern "C" void kernel_launch(void* const* d_in, const int* in_sizes, int n_in,
                              void* d_out, int out_size) {
    (void)in_sizes; (void)n_in; (void)out_size;
    const float* x      = (const float*)d_in[0];
    const float* ln1_g  = (const float*)d_in[3];
    const float* ln1_b  = (const float*)d_in[4];
    const float* qkv_w  = (const float*)d_in[5];
    const float* qkv_b  = (const float*)d_in[6];
    const float* rpb    = (const float*)d_in[7];
    const float* proj_w = (const float*)d_in[8];
    const float* proj_b = (const float*)d_in[9];
    const float* ln2_g  = (const float*)d_in[10];
    const float* ln2_b  = (const float*)d_in[11];
    const float* fc1_w  = (const float*)d_in[12];
    const float* fc1_b  = (const float*)d_in[13];
    const float* bn1_g  = (const float*)d_in[14];
    const float* bn1_b  = (const float*)d_in[15];
    const float* dw_w   = (const float*)d_in[16];
    const float* dw_b   = (const float*)d_in[17];
    const float* bn2_g  = (const float*)d_in[18];
    const float* bn2_b  = (const float*)d_in[19];
    const float* fc2_w  = (const float*)d_in[20];
    const float* fc2_b  = (const float*)d_in[21];
    const float* bn3_g  = (const float*)d_in[22];
    const float* bn3_b  = (const float*)d_in[23];
    float* out = (float*)d_out;

    bf16 *xw, *qkvb, *at, *pj, *h, *z1, *z2, *wq, *wp, *w1, *w2;
    cudaGetSymbolAddress((void**)&xw,   g_xw);
    cudaGetSymbolAddress((void**)&qkvb, g_qkv);
    cudaGetSymbolAddress((void**)&at,   g_at);
    cudaGetSymbolAddress((void**)&pj,   g_pj);
    cudaGetSymbolAddress((void**)&h,    g_h);
    cudaGetSymbolAddress((void**)&z1,   g_z1);
    cudaGetSymbolAddress((void**)&z2,   g_z2);
    cudaGetSymbolAddress((void**)&wq,   g_wq);
    cudaGetSymbolAddress((void**)&wp,   g_wp);
    cudaGetSymbolAddress((void**)&w1,   g_w1);
    cudaGetSymbolAddress((void**)&w2,   g_w2);

    cudaFuncSetAttribute((const void*)hgemm<0, bf16>,  cudaFuncAttributeMaxDynamicSharedMemorySize, SMEMB);
    cudaFuncSetAttribute((const void*)hgemm<1, bf16>,  cudaFuncAttributeMaxDynamicSharedMemorySize, SMEMB);
    cudaFuncSetAttribute((const void*)hgemm<2, float>, cudaFuncAttributeMaxDynamicSharedMemorySize, SMEMB);
    cudaFuncSetAttribute((const void*)attn_win, cudaFuncAttributeMaxDynamicSharedMemorySize, ATT_SMEM);

    f2bf_all<<<(WQ4 + WP4 + W14 + W24 + 255) / 256, 256>>>(qkv_w, proj_w, fc1_w, fc2_w,
                                                           wq, wp, w1, w2);

    ln1_shift_win<<<Tt / 8, 256>>>(x, ln1_g, ln1_b, xw);
    hgemm<0, bf16><<<dim3(1152 / 128, Tt / 128), 128, SMEMB>>>(xw, wq, qkvb, qkv_b,
                                                  nullptr, nullptr, nullptr, nullptr, Tt, 1152, Cc);
    attn_win<<<dim3(1024, HEADS), 128, ATT_SMEM>>>(qkvb, rpb, at);
    hgemm<0, bf16><<<dim3(384 / 128, Tt / 128), 128, SMEMB>>>(at, wp, pj, proj_b,
                                                 nullptr, nullptr, nullptr, nullptr, Tt, Cc, Cc);
    resid_ln2<<<Tt / 8, 256>>>(x, pj, ln2_g, ln2_b, h);
    hgemm<1, bf16><<<dim3(HIDc / 128, Tt / 128), 128, SMEMB>>>(h, w1, z1, fc1_b,
                                                  bn1_g, bn1_b, nullptr, nullptr, Tt, HIDc, Cc);
    dwconv_bn_gelu<<<dim3(Tt / 32, HIDc / 4 / 32), 256>>>(z1, dw_w, dw_b, bn2_g, bn2_b, z2);
    hgemm<2, float><<<dim3(384 / 128, Tt / 128), 128, SMEMB>>>(z2, w2, out, fc2_b,
                                                 bn3_g, bn3_b, x, pj, Tt, Cc, HIDc);
}

// round 17
// speedup vs baseline: 1.4751x; 1.4751x over previous
#include <cuda_runtime.h>
#include <cstdint>
#include <math.h>
#include <mma.h>
#include <cuda_bf16.h>

using namespace nvcuda;

#define Cc    384
#define HEADS 12
#define HIDc  1536
#define Tt    65536          // total tokens = 16*64*64
#define EPSf  1e-5f

#define LDAH  72             // 64 k halfs + 8 pad -> conflict-free ldmatrix
#define LDC   132            // 128 + 4 pad (fp32 C tile)
#define SMEMB (4 * 128 * LDAH * 2)   // 73728 B: 2 stages x {A,B} bf16; C tile (67.6KB) fits

typedef __nv_bfloat16 bf16;

// ---------------- scratch (device globals; no allocation) ----------------
__device__ bf16  g_xw [(size_t)Tt * Cc];        // LN1 out (bf16)
__device__ bf16  g_qkv[(size_t)Tt * 3 * Cc];    // qkv (bf16)
__device__ bf16  g_at [(size_t)Tt * Cc];        // attention out (bf16)
__device__ bf16  g_pj [(size_t)Tt * Cc];        // proj out (bf16, window order)
__device__ bf16  g_h  [(size_t)Tt * Cc];        // LN2 out (bf16)
__device__ bf16  g_z1 [(size_t)Tt * HIDc];      // fc1 out (bf16)
__device__ bf16  g_z2 [(size_t)Tt * HIDc];      // dwconv out (bf16)
__device__ bf16  g_wq [1152 * 384];
__device__ bf16  g_wp [384 * 384];
__device__ bf16  g_w1 [1536 * 384];
__device__ bf16  g_w2 [384 * 1536];

__device__ __forceinline__ float gelu_fast(float x) {
    float u = 0.7978845608028654f * x * (1.0f + 0.044715f * x * x);
    float t;
    asm("tanh.approx.f32 %0, %1;" : "=f"(t) : "f"(u));
    return 0.5f * x * (1.0f + t);
}
__device__ __forceinline__ float warp_sum(float v) {
#pragma unroll
    for (int o = 16; o; o >>= 1) v += __shfl_xor_sync(0xffffffffu, v, o);
    return v;
}
__device__ __forceinline__ void cpa16(void* dst, const void* src) {
    unsigned int s = (unsigned int)__cvta_generic_to_shared(dst);
    asm volatile("cp.async.cg.shared.global [%0], [%1], 16;\n" :: "r"(s), "l"(src));
}
__device__ __forceinline__ void cpa_commit() { asm volatile("cp.async.commit_group;\n"); }
template <int N>
__device__ __forceinline__ void cpa_wait() { asm volatile("cp.async.wait_group %0;\n" :: "n"(N)); }

__device__ __forceinline__ void store4(float* p, float4 v) { *(float4*)p = v; }
__device__ __forceinline__ void store4(bf16* p, float4 v) {
    __nv_bfloat162 lo = __floats2bfloat162_rn(v.x, v.y);
    __nv_bfloat162 hi = __floats2bfloat162_rn(v.z, v.w);
    uint2 u; u.x = *(unsigned int*)&lo; u.y = *(unsigned int*)&hi;
    *(uint2*)p = u;
}
__device__ __forceinline__ float4 load4bf(const bf16* p) {
    uint2 raw = *(const uint2*)p;
    float2 a = __bfloat1622float2(*(__nv_bfloat162*)&raw.x);
    float2 b = __bfloat1622float2(*(__nv_bfloat162*)&raw.y);
    return make_float4(a.x, a.y, b.x, b.y);
}

// ---------------- fused f32 -> bf16 convert of all 4 weight matrices ----------------
#define WQ4 (1152 * 384 / 4)
#define WP4 (384 * 384 / 4)
#define W14 (1536 * 384 / 4)
#define W24 (384 * 1536 / 4)
__global__ void __launch_bounds__(256) f2bf_all(
        const float* __restrict__ qkv_w, const float* __restrict__ proj_w,
        const float* __restrict__ fc1_w, const float* __restrict__ fc2_w,
        bf16* __restrict__ wq, bf16* __restrict__ wp,
        bf16* __restrict__ w1, bf16* __restrict__ w2) {
    int i = blockIdx.x * 256 + threadIdx.x;
    const float* src; bf16* dst; int off;
    if (i < WQ4)                      { src = qkv_w;  dst = wq; off = i; }
    else if (i < WQ4 + WP4)           { src = proj_w; dst = wp; off = i - WQ4; }
    else if (i < WQ4 + WP4 + W14)     { src = fc1_w;  dst = w1; off = i - WQ4 - WP4; }
    else if (i < WQ4 + WP4 + W14 + W24) { src = fc2_w; dst = w2; off = i - WQ4 - WP4 - W14; }
    else return;
    float4 v = *(const float4*)(src + off * 4);
    store4(dst + off * 4, v);
}

// ---------------- 1) LN1 + roll(-4,-4) + window partition -> bf16 ----------------
__global__ void __launch_bounds__(256) ln1_shift_win(
        const float* __restrict__ x, const float* __restrict__ g,
        const float* __restrict__ b, bf16* __restrict__ xw) {
    int warp = threadIdx.x >> 5, lane = threadIdx.x & 31;
    int t = blockIdx.x * 8 + warp;
    int win = t >> 6, n = t & 63;
    int bi = win >> 6, wim = win & 63;
    int r = (((wim >> 3) << 3) + (n >> 3) + 4) & 63;
    int c = (((wim & 7) << 3) + (n & 7) + 4) & 63;
    const float* row = x + ((size_t)bi * 4096 + r * 64 + c) * Cc;
    float v[12]; float s = 0.f;
#pragma unroll
    for (int k = 0; k < 12; k++) { v[k] = row[lane + 32 * k]; s += v[k]; }
    s = warp_sum(s);
    float mean = s * (1.f / 384.f);
    float q = 0.f;
#pragma unroll
    for (int k = 0; k < 12; k++) { float d = v[k] - mean; q += d * d; }
    q = warp_sum(q);
    float rstd = rsqrtf(q * (1.f / 384.f) + EPSf);
    bf16* o = xw + (size_t)t * Cc;
#pragma unroll
    for (int k = 0; k < 12; k++) {
        int idx = lane + 32 * k;
        o[idx] = __float2bfloat16((v[k] - mean) * rstd * g[idx] + b[idx]);
    }
}

// ---------------- 5) un-window + roll(+4,+4) + residual + LN2 (no x1 store) ----------------
__global__ void __launch_bounds__(256) resid_ln2(
        const float* __restrict__ x, const bf16* __restrict__ proj,
        const float* __restrict__ g, const float* __restrict__ b,
        bf16* __restrict__ h) {
    int warp = threadIdx.x >> 5, lane = threadIdx.x & 31;
    int t = blockIdx.x * 8 + warp;
    int bi = t >> 12, l = t & 4095;
    int r = l >> 6, c = l & 63;
    int sr = (r - 4) & 63, sc = (c - 4) & 63;
    int win = bi * 64 + ((sr >> 3) << 3) + (sc >> 3);
    int nn = ((sr & 7) << 3) + (sc & 7);
    const bf16* pr = proj + ((size_t)win * 64 + nn) * Cc;
    const float* xr = x + (size_t)t * Cc;
    float v[12]; float s = 0.f;
#pragma unroll
    for (int k = 0; k < 12; k++) {
        int idx = lane + 32 * k;
        v[k] = xr[idx] + __bfloat162float(pr[idx]);
        s += v[k];
    }
    s = warp_sum(s);
    float mean = s * (1.f / 384.f);
    float q = 0.f;
#pragma unroll
    for (int k = 0; k < 12; k++) { float d = v[k] - mean; q += d * d; }
    q = warp_sum(q);
    float rstd = rsqrtf(q * (1.f / 384.f) + EPSf);
    bf16* o = h + (size_t)t * Cc;
#pragma unroll
    for (int k = 0; k < 12; k++) {
        int idx = lane + 32 * k;
        o[idx] = __float2bfloat16((v[k] - mean) * rstd * g[idx] + b[idx]);
    }
}

// ---------------- 3) windowed attention: one (window, head) per block ----------------
// 128 thr = 4 warps; smem 32 KB: Q[64][40] bf16 @0 | K @5120 | V @10240 | S[64][68] f32 @15360.
#define ATT_SMEM 32768
__global__ void __launch_bounds__(128) attn_win(
        const bf16* __restrict__ qkv, const float* __restrict__ rpb,
        bf16* __restrict__ outp) {
    extern __shared__ char asm_[];
    __shared__ float rps[232];
    __shared__ int labs[64];
    int win = blockIdx.x;
    int head = blockIdx.y;
    int tid = threadIdx.x;
    int warp = tid >> 5;

    bf16* Q = (bf16*)(asm_);
    bf16* K = (bf16*)(asm_ + 5120);
    bf16* V = (bf16*)(asm_ + 10240);
    float* S = (float*)(asm_ + 15360);

#pragma unroll
    for (int i = 0; i < 4; i++) {
        int id = tid + 128 * i;
        int row = id >> 3, c4 = (id & 7) * 4;
        const bf16* src = qkv + ((size_t)win * 64 + row) * (3 * Cc) + head * 32 + c4;
        *(uint2*)(Q + row * 40 + c4) = *(const uint2*)(src);
        *(uint2*)(K + row * 40 + c4) = *(const uint2*)(src + Cc);
        *(uint2*)(V + row * 40 + c4) = *(const uint2*)(src + 2 * Cc);
    }
    for (int i = tid; i < 225; i += 128) rps[i] = rpb[i * HEADS + head];
    if (tid < 64) {
        int n = tid;
        int wim = win & 63;
        int gr = ((wim >> 3) << 3) + (n >> 3);
        int gc = ((wim & 7) << 3) + (n & 7);
        labs[n] = (gr < 56 ? 0 : (gr < 60 ? 1 : 2)) * 3 + (gc < 56 ? 0 : (gc < 60 ? 1 : 2));
    }
    __syncthreads();

    // --- S = Q @ K^T (64x64x32): warp w does rows w*16..+15 ---
    {
        wmma::fragment<wmma::accumulator, 16, 16, 16, float> acc[4];
#pragma unroll
        for (int j = 0; j < 4; j++) wmma::fill_fragment(acc[j], 0.f);
#pragma unroll
        for (int kk = 0; kk < 32; kk += 16) {
            wmma::fragment<wmma::matrix_a, 16, 16, 16, bf16, wmma::row_major> fa;
            wmma::fragment<wmma::matrix_b, 16, 16, 16, bf16, wmma::col_major> fb[4];
            wmma::load_matrix_sync(fa, Q + (warp * 16) * 40 + kk, 40);
#pragma unroll
            for (int j = 0; j < 4; j++)
                wmma::load_matrix_sync(fb[j], K + (j * 16) * 40 + kk, 40);
#pragma unroll
            for (int j = 0; j < 4; j++)
                wmma::mma_sync(acc[j], fa, fb[j], acc[j]);
        }
#pragma unroll
        for (int j = 0; j < 4; j++)
            wmma::store_matrix_sync(S + (warp * 16) * 68 + j * 16, acc[j], 68,
                                    wmma::mem_row_major);
    }
    __syncthreads();

    // --- softmax: threads 0..63, one row each; float4 LDS; write P (bf16) over Q/K ---
    if (tid < 64) {
        int n = tid;
        bf16* P = (bf16*)asm_;
        const float SC = 0.17677669529663687f;   // 1/sqrt(32)
        int cvn = 15 * (n >> 3) + (n & 7);
        int myl = labs[n];
        float s[64];
        float mx = -1e30f;
#pragma unroll
        for (int m = 0; m < 64; m += 4) {
            float4 sv = *(const float4*)(S + n * 68 + m);
#pragma unroll
            for (int u = 0; u < 4; u++) {
                int mm = 63 - (m + u);
                int cvm = 15 * (mm >> 3) + (mm & 7);
                float a = (u == 0 ? sv.x : u == 1 ? sv.y : u == 2 ? sv.z : sv.w);
                a = a * SC + rps[cvn + cvm];
                a += (labs[m + u] != myl) ? -100.f : 0.f;
                s[m + u] = a;
                mx = fmaxf(mx, a);
            }
        }
        float sum = 0.f;
#pragma unroll
        for (int m = 0; m < 64; m++) { float e = __expf(s[m] - mx); s[m] = e; sum += e; }
        float inv = 1.f / sum;
#pragma unroll
        for (int m = 0; m < 64; m += 2) {
            __nv_bfloat162 pr2 = __floats2bfloat162_rn(s[m] * inv, s[m + 1] * inv);
            *(__nv_bfloat162*)(P + n * 72 + m) = pr2;
        }
    }
    __syncthreads();

    // --- O = P @ V (64x32x64): warp w rows w*16..+15; result into S ---
    {
        bf16* P = (bf16*)asm_;
        wmma::fragment<wmma::accumulator, 16, 16, 16, float> acc[2];
#pragma unroll
        for (int j = 0; j < 2; j++) wmma::fill_fragment(acc[j], 0.f);
#pragma unroll
        for (int kk = 0; kk < 64; kk += 16) {
            wmma::fragment<wmma::matrix_a, 16, 16, 16, bf16, wmma::row_major> fa;
            wmma::fragment<wmma::matrix_b, 16, 16, 16, bf16, wmma::row_major> fb[2];
            wmma::load_matrix_sync(fa, P + (warp * 16) * 72 + kk, 72);
#pragma unroll
            for (int j = 0; j < 2; j++)
                wmma::load_matrix_sync(fb[j], V + kk * 40 + j * 16, 40);
#pragma unroll
            for (int j = 0; j < 2; j++)
                wmma::mma_sync(acc[j], fa, fb[j], acc[j]);
        }
#pragma unroll
        for (int j = 0; j < 2; j++)
            wmma::store_matrix_sync(S + (warp * 16) * 68 + j * 16, acc[j], 68,
                                    wmma::mem_row_major);
    }
    __syncthreads();

#pragma unroll
    for (int i = 0; i < 4; i++) {
        int id = tid + 128 * i;
        int row = id >> 3, c4 = (id & 7) * 4;
        float4 v = *(const float4*)(S + row * 68 + c4);
        store4(outp + ((size_t)win * 64 + row) * Cc + head * 32 + c4, v);
    }
}

// ---------------- bf16 tensor-core GEMM, 2-stage cp.async, 3 CTAs/SM ----------------
// MODE 0: +bias  1: gelu(bn(+bias))
// MODE 2: gelu(bn(+bias)) + (x + unwindow(pj))  — recomputes the residual in-epilogue
template <int MODE, typename OUTT>
__global__ void __launch_bounds__(128, 3) hgemm(
        const bf16* __restrict__ A, const bf16* __restrict__ Wt,
        OUTT* __restrict__ Co, const float* __restrict__ bias,
        const float* __restrict__ bng, const float* __restrict__ bnb,
        const float* __restrict__ resx, const bf16* __restrict__ respj,
        int M, int Nn, int K) {
    extern __shared__ char smraw[];
    bf16* smh = (bf16*)smraw;
    bf16* Abuf[2] = { smh, smh + 2 * 128 * LDAH };
    bf16* Bbuf[2] = { smh + 128 * LDAH, smh + 3 * 128 * LDAH };

    int tid = threadIdx.x;
    int warp = tid >> 5;
    int wm = warp >> 1;
    int wn = warp & 1;
    int rowA = blockIdx.y * 128;
    int rowB = blockIdx.x * 128;

    wmma::fragment<wmma::accumulator, 16, 16, 16, float> acc[4][4];
#pragma unroll
    for (int i = 0; i < 4; i++)
#pragma unroll
        for (int j = 0; j < 4; j++) wmma::fill_fragment(acc[i][j], 0.f);

    int lrow = tid >> 3, lc = (tid & 7) * 8;
    const bf16* Ag = A  + (size_t)(rowA + lrow) * K + lc;
    const bf16* Bg = Wt + (size_t)(rowB + lrow) * K + lc;
    int nk = K >> 6;

    // prologue: stage 0
#pragma unroll
    for (int r = 0; r < 8; r++) {
        cpa16(Abuf[0] + (lrow + 16 * r) * LDAH + lc, Ag + (size_t)(16 * r) * K);
        cpa16(Bbuf[0] + (lrow + 16 * r) * LDAH + lc, Bg + (size_t)(16 * r) * K);
    }
    cpa_commit();

    for (int s = 0; s < nk; s++) {
        int cur = s & 1;
        if (s + 1 < nk) {
            int nb = cur ^ 1;
            int k0 = (s + 1) << 6;
#pragma unroll
            for (int r = 0; r < 8; r++) {
                cpa16(Abuf[nb] + (lrow + 16 * r) * LDAH + lc, Ag + (size_t)(16 * r) * K + k0);
                cpa16(Bbuf[nb] + (lrow + 16 * r) * LDAH + lc, Bg + (size_t)(16 * r) * K + k0);
            }
            cpa_commit();
            cpa_wait<1>();
        } else {
            cpa_wait<0>();
        }
        __syncthreads();
#pragma unroll
        for (int kk = 0; kk < 64; kk += 16) {
            wmma::fragment<wmma::matrix_a, 16, 16, 16, bf16, wmma::row_major> fa[4];
            wmma::fragment<wmma::matrix_b, 16, 16, 16, bf16, wmma::col_major> fb[4];
#pragma unroll
            for (int i = 0; i < 4; i++)
                wmma::load_matrix_sync(fa[i], Abuf[cur] + (wm * 64 + i * 16) * LDAH + kk, LDAH);
#pragma unroll
            for (int j = 0; j < 4; j++)
                wmma::load_matrix_sync(fb[j], Bbuf[cur] + (wn * 64 + j * 16) * LDAH + kk, LDAH);
#pragma unroll
            for (int i = 0; i < 4; i++)
#pragma unroll
                for (int j = 0; j < 4; j++)
                    wmma::mma_sync(acc[i][j], fa[i], fb[j], acc[i][j]);
        }
        __syncthreads();
    }

    // epilogue through fp32 smem C tile (reuses stage buffers)
    float* Cs = (float*)smraw;
#pragma unroll
    for (int i = 0; i < 4; i++)
#pragma unroll
        for (int j = 0; j < 4; j++)
            wmma::store_matrix_sync(Cs + (wm * 64 + i * 16) * LDC + wn * 64 + j * 16,
                                    acc[i][j], LDC, wmma::mem_row_major);
    __syncthreads();

    const float IS = rsqrtf(1.0f + EPSf);
    int q = tid & 31;
    int r0 = tid >> 5;
    int ncol = rowB + q * 4;
    float4 bv = *(const float4*)(bias + ncol);
    float4 gv = make_float4(0.f, 0.f, 0.f, 0.f), bb = gv;
    if (MODE >= 1) {
        gv = *(const float4*)(bng + ncol);
        bb = *(const float4*)(bnb + ncol);
        gv.x *= IS; gv.y *= IS; gv.z *= IS; gv.w *= IS;
    }
#pragma unroll
    for (int it = 0; it < 32; it++) {
        int r = r0 + it * 4;
        float4 v = *(const float4*)(Cs + r * LDC + q * 4);
        v.x += bv.x; v.y += bv.y; v.z += bv.z; v.w += bv.w;
        if (MODE >= 1) {
            v.x = gelu_fast(v.x * gv.x + bb.x);
            v.y = gelu_fast(v.y * gv.y + bb.y);
            v.z = gelu_fast(v.z * gv.z + bb.z);
            v.w = gelu_fast(v.w * gv.w + bb.w);
        }
        size_t off = (size_t)(rowA + r) * Nn + ncol;
        if (MODE == 2) {
            int t = rowA + r;
            int bi = t >> 12, l = t & 4095;
            int rr = l >> 6, cc = l & 63;
            int sr = (rr - 4) & 63, sc = (cc - 4) & 63;
            int win = bi * 64 + ((sr >> 3) << 3) + (sc >> 3);
            int nn = ((sr & 7) << 3) + (sc & 7);
            float4 xv = *(const float4*)(resx + off);
            float4 pv = load4bf(respj + ((size_t)win * 64 + nn) * Cc + ncol);
            v.x += xv.x + pv.x; v.y += xv.y + pv.y;
            v.z += xv.z + pv.z; v.w += xv.w + pv.w;
        }
        store4(Co + off, v);
    }
}

// ---------------- 7) NHWC depthwise 3x3 + BN + GELU, 4 pixels/thread ----------------
__global__ void __launch_bounds__(256) dwconv_bn_gelu(
        const bf16* __restrict__ z1, const float* __restrict__ wt,
        const float* __restrict__ wb, const float* __restrict__ bng,
        const float* __restrict__ bnb, bf16* __restrict__ z2) {
    __shared__ float ws[9][4][32];
    int c4l = threadIdx.x & 31;
    int p   = threadIdx.x >> 5;              // 0..7
    int ch  = (blockIdx.y * 32 + c4l) * 4;
    for (int i = threadIdx.x; i < 1152; i += 256) {
        int cc = i & 31;
        int l  = (i >> 5) & 3;
        int k  = i >> 7;
        ws[k][l][cc] = wt[(((blockIdx.y * 32 + cc) * 4) + l) * 9 + k];
    }
    __syncthreads();

    int pixbase = blockIdx.x * 32 + p * 4;
    int bi = pixbase >> 12; int rc = pixbase & 4095;
    int r = rc >> 6, c = rc & 63;
    float4 acc[4];
#pragma unroll
    for (int i = 0; i < 4; i++) acc[i] = make_float4(0.f, 0.f, 0.f, 0.f);

#pragma unroll
    for (int dr = -1; dr <= 1; dr++) {
        int rr = r + dr;
        if (rr < 0 || rr > 63) continue;
        const bf16* rowp = z1 + ((size_t)(bi * 4096 + rr * 64)) * HIDc + ch;
        int kb = (dr + 1) * 3;
#pragma unroll
        for (int j = -1; j <= 4; j++) {
            int cc = c + j;
            if (cc < 0 || cc > 63) continue;
            float4 v = load4bf(rowp + (size_t)cc * HIDc);
#pragma unroll
            for (int i = 0; i < 4; i++) {
                int d = j - i;
                if (d < -1 || d > 1) continue;
                int k = kb + d + 1;
                acc[i].x += v.x * ws[k][0][c4l];
                acc[i].y += v.y * ws[k][1][c4l];
                acc[i].z += v.z * ws[k][2][c4l];
                acc[i].w += v.w * ws[k][3][c4l];
            }
        }
    }
    const float IS = rsqrtf(1.0f + EPSf);
    float b0 = wb[ch + 0], b1 = wb[ch + 1], b2 = wb[ch + 2], b3 = wb[ch + 3];
    float g0 = bng[ch + 0] * IS, g1 = bng[ch + 1] * IS, g2 = bng[ch + 2] * IS, g3 = bng[ch + 3] * IS;
    float c0 = bnb[ch + 0], c1 = bnb[ch + 1], c2 = bnb[ch + 2], c3 = bnb[ch + 3];
#pragma unroll
    for (int i = 0; i < 4; i++) {
        float4 o;
        o.x = gelu_fast((acc[i].x + b0) * g0 + c0);
        o.y = gelu_fast((acc[i].y + b1) * g1 + c1);
        o.z = gelu_fast((acc[i].z + b2) * g2 + c2);
        o.w = gelu_fast((acc[i].w + b3) * g3 + c3);
        store4(z2 + (size_t)(pixbase + i) * HIDc + ch, o);
    }
}

// ---------------- launcher ----------------
extern "C" void kernel_launch(void* const* d_in, const int* in_sizes, int n_in,
                              void* d_out, int out_size) {
    (void)in_sizes; (void)n_in; (void)out_size;
    const float* x      = (const float*)d_in[0];
    const float* ln1_g  = (const float*)d_in[3];
    const float* ln1_b  = (const float*)d_in[4];
    const float* qkv_w  = (const float*)d_in[5];
    const float* qkv_b  = (const float*)d_in[6];
    const float* rpb    = (const float*)d_in[7];
    const float* proj_w = (const float*)d_in[8];
    const float* proj_b = (const float*)d_in[9];
    const float* ln2_g  = (const float*)d_in[10];
    const float* ln2_b  = (const float*)d_in[11];
    const float* fc1_w  = (const float*)d_in[12];
    const float* fc1_b  = (const float*)d_in[13];
    const float* bn1_g  = (const float*)d_in[14];
    const float* bn1_b  = (const float*)d_in[15];
    const float* dw_w   = (const float*)d_in[16];
    const float* dw_b   = (const float*)d_in[17];
    const float* bn2_g  = (const float*)d_in[18];
    const float* bn2_b  = (const float*)d_in[19];
    const float* fc2_w  = (const float*)d_in[20];
    const float* fc2_b  = (const float*)d_in[21];
    const float* bn3_g  = (const float*)d_in[22];
    const float* bn3_b  = (const float*)d_in[23];
    float* out = (float*)d_out;

    bf16 *xw, *qkvb, *at, *pj, *h, *z1, *z2, *wq, *wp, *w1, *w2;
    cudaGetSymbolAddress((void**)&xw,   g_xw);
    cudaGetSymbolAddress((void**)&qkvb, g_qkv);
    cudaGetSymbolAddress((void**)&at,   g_at);
    cudaGetSymbolAddress((void**)&pj,   g_pj);
    cudaGetSymbolAddress((void**)&h,    g_h);
    cudaGetSymbolAddress((void**)&z1,   g_z1);
    cudaGetSymbolAddress((void**)&z2,   g_z2);
    cudaGetSymbolAddress((void**)&wq,   g_wq);
    cudaGetSymbolAddress((void**)&wp,   g_wp);
    cudaGetSymbolAddress((void**)&w1,   g_w1);
    cudaGetSymbolAddress((void**)&w2,   g_w2);

    cudaFuncSetAttribute((const void*)hgemm<0, bf16>,  cudaFuncAttributeMaxDynamicSharedMemorySize, SMEMB);
    cudaFuncSetAttribute((const void*)hgemm<1, bf16>,  cudaFuncAttributeMaxDynamicSharedMemorySize, SMEMB);
    cudaFuncSetAttribute((const void*)hgemm<2, float>, cudaFuncAttributeMaxDynamicSharedMemorySize, SMEMB);
    cudaFuncSetAttribute((const void*)attn_win, cudaFuncAttributeMaxDynamicSharedMemorySize, ATT_SMEM);

    f2bf_all<<<(WQ4 + WP4 + W14 + W24 + 255) / 256, 256>>>(qkv_w, proj_w, fc1_w, fc2_w,
                                                           wq, wp, w1, w2);

    ln1_shift_win<<<Tt / 8, 256>>>(x, ln1_g, ln1_b, xw);
    hgemm<0, bf16><<<dim3(1152 / 128, Tt / 128), 128, SMEMB>>>(xw, wq, qkvb, qkv_b,
                                                  nullptr, nullptr, nullptr, nullptr, Tt, 1152, Cc);
    attn_win<<<dim3(1024, HEADS), 128, ATT_SMEM>>>(qkvb, rpb, at);
    hgemm<0, bf16><<<dim3(384 / 128, Tt / 128), 128, SMEMB>>>(at, wp, pj, proj_b,
                                                 nullptr, nullptr, nullptr, nullptr, Tt, Cc, Cc);
    resid_ln2<<<Tt / 8, 256>>>(x, pj, ln2_g, ln2_b, h);
    hgemm<1, bf16><<<dim3(HIDc / 128, Tt / 128), 128, SMEMB>>>(h, w1, z1, fc1_b,
                                                  bn1_g, bn1_b, nullptr, nullptr, Tt, HIDc, Cc);
    dwconv_bn_gelu<<<dim3(Tt / 32, HIDc / 4 / 32), 256>>>(z1, dw_w, dw_b, bn2_g, bn2_b, z2);
    hgemm<2, float><<<dim3(384 / 128, Tt / 128), 128, SMEMB>>>(z2, w2, out, fc2_b,
                                                 bn3_g, bn3_b, x, pj, Tt, Cc, HIDc);
}